// round 1
// baseline (speedup 1.0000x reference)
#include <cuda_runtime.h>
#include <cstdint>

#define RES   128
#define FEAT  32
#define OUTF  4
#define NVOX  (RES * RES * RES)           // 2,097,152 voxels
#define NPTS  (2048 * 1024)               // 2,097,152 points
#define PTS_PER_BLOCK 256

// Voxel-major scratch: vox[v*32 + c], one 128B line per voxel.
__device__ float g_vox[(size_t)NVOX * FEAT];

// ---------------------------------------------------------------------------
// Kernel 1: transpose grid (C, D, H, W) -> (D*H*W, C)
// Treat as 32 x NVOX matrix transpose with 32x32 shared tiles.
// ---------------------------------------------------------------------------
__global__ void __launch_bounds__(256) transpose_grid_kernel(const float* __restrict__ g) {
    __shared__ float tile[32][33];
    const int v0 = blockIdx.x * 32;
    const int tx = threadIdx.x;   // 0..31
    const int ty = threadIdx.y;   // 0..7

#pragma unroll
    for (int i = 0; i < 4; i++) {
        int c = ty + i * 8;
        tile[c][tx] = g[(size_t)c * NVOX + v0 + tx];   // coalesced along voxels
    }
    __syncthreads();
#pragma unroll
    for (int i = 0; i < 4; i++) {
        int v = ty + i * 8;
        g_vox[(size_t)(v0 + v) * FEAT + tx] = tile[tx][v];  // coalesced along channels
    }
}

// ---------------------------------------------------------------------------
// Kernel 2: fused trilinear gather + 4-layer MLP.
// Block = 256 threads = 256 points.
// Phase 1: warp-cooperative gather. Each warp handles 32 points in 8 rounds
//          of 4 points; lane = (point_in_4 << 3) | chunk, chunk = 4-channel
//          float4 slice. One LDG.128 per corner per 4 points -> 4 lines/inst.
// Phase 2: per-thread MLP, v/h in registers, weights broadcast from smem.
// ---------------------------------------------------------------------------
__global__ void __launch_bounds__(256) fused_field_kernel(
    const float* __restrict__ coord,
    const float* __restrict__ w1, const float* __restrict__ b1,
    const float* __restrict__ w2, const float* __restrict__ b2,
    const float* __restrict__ w3, const float* __restrict__ b3,
    const float* __restrict__ w4, const float* __restrict__ b4,
    float* __restrict__ out)
{
    __shared__ float4 sv[8][PTS_PER_BLOCK];     // [chunk][point]   32 KB
    __shared__ float4 sW1[256], sW2[256], sW3[256], sW4[32];
    __shared__ float  sB1[32], sB2[32], sB3[32], sB4[4];

    const int tid = threadIdx.x;

    // --- cooperative weight load ---
    {
        const float4* w1v = (const float4*)w1;
        const float4* w2v = (const float4*)w2;
        const float4* w3v = (const float4*)w3;
        if (tid < 256) { sW1[tid] = w1v[tid]; sW2[tid] = w2v[tid]; sW3[tid] = w3v[tid]; }
        if (tid < 32)  { sW4[tid] = ((const float4*)w4)[tid]; sB1[tid] = b1[tid]; sB2[tid] = b2[tid]; sB3[tid] = b3[tid]; }
        if (tid < 4)   { sB4[tid] = b4[tid]; }
    }

    // --- Phase 1: gather ---
    const int warp  = tid >> 5;
    const int lane  = tid & 31;
    const int chunk = lane & 7;        // which float4 of the 32 channels
    const int psub  = lane >> 3;       // which of 4 points in this round

#pragma unroll 1
    for (int s = 0; s < 8; s++) {
        const int q   = (warp << 5) + (s << 2) + psub;           // point in block
        const int pid = blockIdx.x * PTS_PER_BLOCK + q;

        const float cx = __ldg(&coord[pid * 3 + 0]);
        const float cy = __ldg(&coord[pid * 3 + 1]);
        const float cz = __ldg(&coord[pid * 3 + 2]);

        // fx = ((x+1)*W - 1) * 0.5 = (x+1)*64 - 0.5
        const float fx = (cx + 1.0f) * 64.0f - 0.5f;
        const float fy = (cy + 1.0f) * 64.0f - 0.5f;
        const float fz = (cz + 1.0f) * 64.0f - 0.5f;

        const float x0f = floorf(fx), y0f = floorf(fy), z0f = floorf(fz);
        const float tx = fx - x0f, ty = fy - y0f, tz = fz - z0f;
        const int x0 = (int)x0f, y0 = (int)y0f, z0 = (int)z0f;

        int   xs[2], ys[2], zs[2];
        float wx[2], wy[2], wz[2];
        xs[0] = max(x0, 0);       xs[1] = min(x0 + 1, RES - 1);
        ys[0] = max(y0, 0);       ys[1] = min(y0 + 1, RES - 1);
        zs[0] = max(z0, 0);       zs[1] = min(z0 + 1, RES - 1);
        wx[0] = (x0 >= 0)        ? (1.0f - tx) : 0.0f;
        wx[1] = (x0 + 1 <= RES-1)? tx          : 0.0f;
        wy[0] = (y0 >= 0)        ? (1.0f - ty) : 0.0f;
        wy[1] = (y0 + 1 <= RES-1)? ty          : 0.0f;
        wz[0] = (z0 >= 0)        ? (1.0f - tz) : 0.0f;
        wz[1] = (z0 + 1 <= RES-1)? tz          : 0.0f;

        float4 acc = make_float4(0.f, 0.f, 0.f, 0.f);
#pragma unroll
        for (int kz = 0; kz < 2; kz++) {
#pragma unroll
            for (int ky = 0; ky < 2; ky++) {
#pragma unroll
                for (int kx = 0; kx < 2; kx++) {
                    const float w = wz[kz] * wy[ky] * wx[kx];
                    const int   vox = ((zs[kz] * RES + ys[ky]) * RES + xs[kx]);
                    const float4 gv = __ldg(((const float4*)(g_vox + (size_t)vox * FEAT)) + chunk);
                    acc.x = fmaf(w, gv.x, acc.x);
                    acc.y = fmaf(w, gv.y, acc.y);
                    acc.z = fmaf(w, gv.z, acc.z);
                    acc.w = fmaf(w, gv.w, acc.w);
                }
            }
        }
        sv[chunk][q] = acc;
    }

    __syncthreads();

    // --- Phase 2: MLP (one thread per point) ---
    float v[32], h[32];
#pragma unroll
    for (int m = 0; m < 8; m++) {
        float4 f = sv[m][tid];
        v[4*m+0] = f.x; v[4*m+1] = f.y; v[4*m+2] = f.z; v[4*m+3] = f.w;
    }

    // layer 1: h = relu(W1 v + b1)
#pragma unroll
    for (int j = 0; j < 32; j++) {
        float a = sB1[j];
#pragma unroll
        for (int i = 0; i < 8; i++) {
            float4 ww = sW1[j * 8 + i];
            a = fmaf(ww.x, v[4*i+0], a);
            a = fmaf(ww.y, v[4*i+1], a);
            a = fmaf(ww.z, v[4*i+2], a);
            a = fmaf(ww.w, v[4*i+3], a);
        }
        h[j] = fmaxf(a, 0.0f);
    }
    // layer 2: v = relu(W2 h + b2)
#pragma unroll
    for (int j = 0; j < 32; j++) {
        float a = sB2[j];
#pragma unroll
        for (int i = 0; i < 8; i++) {
            float4 ww = sW2[j * 8 + i];
            a = fmaf(ww.x, h[4*i+0], a);
            a = fmaf(ww.y, h[4*i+1], a);
            a = fmaf(ww.z, h[4*i+2], a);
            a = fmaf(ww.w, h[4*i+3], a);
        }
        v[j] = fmaxf(a, 0.0f);
    }
    // layer 3: h = relu(W3 v + b3)
#pragma unroll
    for (int j = 0; j < 32; j++) {
        float a = sB3[j];
#pragma unroll
        for (int i = 0; i < 8; i++) {
            float4 ww = sW3[j * 8 + i];
            a = fmaf(ww.x, v[4*i+0], a);
            a = fmaf(ww.y, v[4*i+1], a);
            a = fmaf(ww.z, v[4*i+2], a);
            a = fmaf(ww.w, v[4*i+3], a);
        }
        h[j] = fmaxf(a, 0.0f);
    }
    // layer 4: out = W4 h + b4  (4 outputs)
    float o[4];
#pragma unroll
    for (int j = 0; j < 4; j++) {
        float a = sB4[j];
#pragma unroll
        for (int i = 0; i < 8; i++) {
            float4 ww = sW4[j * 8 + i];
            a = fmaf(ww.x, h[4*i+0], a);
            a = fmaf(ww.y, h[4*i+1], a);
            a = fmaf(ww.z, h[4*i+2], a);
            a = fmaf(ww.w, h[4*i+3], a);
        }
        o[j] = a;
    }

    const int pid = blockIdx.x * PTS_PER_BLOCK + tid;
    ((float4*)out)[pid] = make_float4(o[0], o[1], o[2], o[3]);
}

// ---------------------------------------------------------------------------
extern "C" void kernel_launch(void* const* d_in, const int* in_sizes, int n_in,
                              void* d_out, int out_size)
{
    const float* coord = (const float*)d_in[0];
    const float* grid  = (const float*)d_in[1];
    const float* w1    = (const float*)d_in[2];
    const float* b1    = (const float*)d_in[3];
    const float* w2    = (const float*)d_in[4];
    const float* b2    = (const float*)d_in[5];
    const float* w3    = (const float*)d_in[6];
    const float* b3    = (const float*)d_in[7];
    const float* w4    = (const float*)d_in[8];
    const float* b4    = (const float*)d_in[9];
    float* out = (float*)d_out;

    // 1) transpose grid into voxel-major scratch
    dim3 tb(32, 8);
    transpose_grid_kernel<<<NVOX / 32, tb>>>(grid);

    // 2) fused gather + MLP
    fused_field_kernel<<<NPTS / PTS_PER_BLOCK, PTS_PER_BLOCK>>>(
        coord, w1, b1, w2, b2, w3, b3, w4, b4, out);
}